// round 16
// baseline (speedup 1.0000x reference)
#include <cuda_runtime.h>
#include <math.h>

#define HW 384
#define NE 147456
#define BB 4
#define CC 8
typedef unsigned long long ull;

__device__ float  g_actA[BB*64*NE];
__device__ float  g_actB[BB*64*NE];
__device__ float  g_xplane[BB*2*NE];
__device__ float  g_hplane[BB*2*NE];
__device__ float2 g_tmp[BB*CC*NE];
__device__ float2 g_r[BB*NE];
__device__ float2 g_p[BB*NE];
__device__ float2 g_xc[BB*NE];
__device__ float2 g_Ap[BB*NE];
__device__ float  g_part1[BB*384];
__device__ float  g_part2[BB*384];
__device__ float  g_rTr[BB];
__device__ float  g_alpha[BB];
__device__ float  g_beta[BB];
__device__ float2 g_tw[384];
// duplicated weights: conv_in [ci(2)][oc64][9] then 7 mid convs [ci64][oc64][9]
__device__ float2 g_wdup[1152 + 7*36864];

__device__ __forceinline__ ull pk2(float a, float b){
    ull r; asm("mov.b64 %0, {%1, %2};" : "=l"(r) : "f"(a), "f"(b)); return r;
}
__device__ __forceinline__ float2 up2(ull v){
    float2 r; asm("mov.b64 {%0, %1}, %2;" : "=f"(r.x), "=f"(r.y) : "l"(v)); return r;
}
__device__ __forceinline__ void ffma2(ull &d, ull a, ull b){
    asm("fma.rn.f32x2 %0, %1, %2, %0;" : "+l"(d) : "l"(a), "l"(b));
}
__device__ __forceinline__ void cpa4(unsigned s, const void* g){
    asm volatile("cp.async.ca.shared.global [%0], [%1], 4;" :: "r"(s), "l"(g));
}
__device__ __forceinline__ void cpa8(unsigned s, const void* g){
    asm volatile("cp.async.ca.shared.global [%0], [%1], 8;" :: "r"(s), "l"(g));
}
__device__ __forceinline__ void cpcommit(){ asm volatile("cp.async.commit_group;"); }
template<int N> __device__ __forceinline__ void cpwait(){
    asm volatile("cp.async.wait_group %0;" :: "n"(N));
}
__device__ __forceinline__ float2 f2add(float2 a, float2 b){ return make_float2(a.x+b.x, a.y+b.y); }
__device__ __forceinline__ float2 f2sub(float2 a, float2 b){ return make_float2(a.x-b.x, a.y-b.y); }
__device__ __forceinline__ float2 f2mul(float2 a, float2 b){
    return make_float2(a.x*b.x - a.y*b.y, a.x*b.y + a.y*b.x);
}
__device__ __forceinline__ int perm384(int i){
    return 3*(int)(__brev((unsigned)(i & 127)) >> 25) + (i >> 7);
}

// 384-pt FFT: input pre-permuted via perm384, blockDim.x == 128
__device__ void fft384(float2* Y, int t, bool inv)
{
#pragma unroll
    for (int s = 0; s < 7; s++){
        const int half = 1 << s;
#pragma unroll
        for (int kk = 0; kk < 2; kk++){
            int k = t + kk*128;
            if (k < 192){
                int sub = k >> 6, j = k & 63;
                int jl = j & (half - 1);
                int i0 = (sub << 7) + (((j >> s) << (s+1)) | jl);
                float2 w = g_tw[3*(jl << (6 - s))];
                if (inv) w.y = -w.y;
                float2 a = Y[i0], b = Y[i0 + half];
                float2 wb = f2mul(b, w);
                Y[i0]        = f2add(a, wb);
                Y[i0 + half] = f2sub(a, wb);
            }
        }
        __syncthreads();
    }
    {
        int m = t;
        float2 w1 = g_tw[m], w2 = g_tw[2*m];
        if (inv){ w1.y = -w1.y; w2.y = -w2.y; }
        float2 G0 = Y[m];
        float2 G1 = f2mul(Y[128 + m], w1);
        float2 G2 = f2mul(Y[256 + m], w2);
        const float wi = inv ? 0.86602540378443864676f : -0.86602540378443864676f;
        float2 A  = f2add(G1, G2);
        float2 Bd = f2sub(G1, G2);
        float2 X0 = f2add(G0, A);
        float2 T  = make_float2(G0.x - 0.5f*A.x, G0.y - 0.5f*A.y);
        float2 X1 = make_float2(T.x - wi*Bd.y, T.y + wi*Bd.x);
        float2 X2 = make_float2(T.x + wi*Bd.y, T.y - wi*Bd.x);
        if (inv){
            const float sc = 1.0f/384.0f;
            X0.x*=sc; X0.y*=sc; X1.x*=sc; X1.y*=sc; X2.x*=sc; X2.y*=sc;
        }
        __syncthreads();
        Y[m] = X0; Y[128 + m] = X1; Y[256 + m] = X2;
    }
    __syncthreads();
}

__global__ void k_twinit(){
    int t = threadIdx.x;
    if (t < 384){
        double th = -2.0 * 3.141592653589793238462643383279502884 * (double)t / 384.0;
        g_tw[t] = make_float2((float)cos(th), (float)sin(th));
    }
}
__global__ void k_copy(const float* __restrict__ src){
    int i = blockIdx.x*256 + threadIdx.x;
    if (i < BB*2*NE) g_xplane[i] = src[i];
}
// build duplicated-weight table
__global__ void k_wdup(const float* __restrict__ w_in, const float* __restrict__ ws_mid){
    int idx = blockIdx.x*256 + threadIdx.x;
    if (idx < 1152){
        int tap = idx % 9; int r = idx / 9;
        int oc = r % 64, ci = r / 64;
        float v = w_in[(size_t)(oc*2 + ci)*9 + tap];
        g_wdup[idx] = make_float2(v, v);
    }
    int m = idx - 1152;
    if (m >= 0 && m < 7*36864){
        int tap = m % 9; int r = m / 9;
        int oc = r % 64; r /= 64;
        int ci = r % 64; int v5 = r / 64;
        float v = ws_mid[((size_t)(v5*64 + oc)*64 + ci)*9 + tap];
        g_wdup[1152 + m] = make_float2(v, v);
    }
}

// ---------------- conv 3x3 SAME, chunked double-buffered ----------
// block 256 = tx(4) x ty(32) x tz(2); tile 32x32; thread: 8 px x 4 oc (f32x2)
// block covers 8 oc (ocg in 0..7); 4 input channels per barrier pair.
template<int CIN, bool RELU>
__global__ void __launch_bounds__(256, 2) conv_k(const float* __restrict__ in,
                                                 float* __restrict__ out,
                                                 const float2* __restrict__ wd,
                                                 const float* __restrict__ bias)
{
    constexpr int CH  = (CIN >= 4) ? 4 : CIN;   // channels per chunk
    constexpr int NCH = CIN / CH;               // number of chunks
    __shared__ float  s_in[2][CH*1224];         // 34*36 = 1224 floats per plane
    __shared__ float2 s_w[2][CH*72];            // 8 oc x 9 taps per plane
    const int tid = threadIdx.x;
    const int tx = tid & 3;
    const int ty = (tid >> 2) & 31;
    const int tz = tid >> 7;
    const int gx0 = blockIdx.x*32, gy0 = blockIdx.y*32;
    const int b = blockIdx.z >> 3, ocg = blockIdx.z & 7;

    // per-thread fixed tile-load slots (1156 elems per plane)
    int soff[5], goff[5];
#pragma unroll
    for (int k = 0; k < 5; k++){
        int i = tid + 256*k;
        soff[k] = -1; goff[k] = -1;
        if (i < 1156){
            int rr = i / 34, cc = i - rr*34;
            soff[k] = rr*36 + cc;
            int yy = gy0 - 1 + rr, xx = gx0 - 1 + cc;
            if ((unsigned)yy < 384u && (unsigned)xx < 384u) goff[k] = yy*384 + xx;
        }
    }

    ull acc[4][4];
#pragma unroll
    for (int o = 0; o < 4; o++)
#pragma unroll
        for (int j = 0; j < 4; j++) acc[o][j] = 0ULL;

    const float* inb = in + (size_t)b*CIN*NE;

    auto pref = [&](int bi, int c0){
        unsigned sb = (unsigned)__cvta_generic_to_shared(&s_in[bi][0]);
        unsigned sw = (unsigned)__cvta_generic_to_shared(&s_w[bi][0]);
#pragma unroll
        for (int k = 0; k < 5; k++){
            if (soff[k] >= 0){
#pragma unroll
                for (int q = 0; q < CH; q++){
                    unsigned sa = sb + (unsigned)(q*1224 + soff[k])*4u;
                    if (goff[k] >= 0) cpa4(sa, inb + (size_t)(c0+q)*NE + goff[k]);
                    else {
                        float z = 0.f;
                        asm volatile("st.shared.f32 [%0], %1;" :: "r"(sa), "f"(z));
                    }
                }
            }
        }
#pragma unroll
        for (int w = tid; w < CH*72; w += 256){
            int q = w / 72, rwi = w - q*72;
            cpa8(sw + (unsigned)w*8u, wd + (size_t)(c0+q)*576 + ocg*72 + rwi);
        }
    };

    auto comp = [&](int bi){
#pragma unroll
        for (int q = 0; q < CH; q++){
            const float*  sbuf = &s_in[bi][q*1224];
            const float2* wrow = &s_w[bi][q*72 + tz*36];
#pragma unroll
            for (int dy = 0; dy < 3; dy++){
                const float* row = &sbuf[(ty+dy)*36 + tx*8];
                float4 a4 = *(const float4*)row;
                float4 b4 = *(const float4*)(row + 4);
                float2 c2 = *(const float2*)(row + 8);
                float v[10] = {a4.x, a4.y, a4.z, a4.w, b4.x, b4.y, b4.z, b4.w, c2.x, c2.y};
                ull vp[9];
#pragma unroll
                for (int k = 0; k < 9; k++) vp[k] = pk2(v[k], v[k+1]);
#pragma unroll
                for (int dx = 0; dx < 3; dx++){
#pragma unroll
                    for (int o = 0; o < 4; o++){
                        ull wp = *reinterpret_cast<const ull*>(&wrow[o*9 + dy*3 + dx]);
                        ffma2(acc[o][0], vp[dx+0], wp);
                        ffma2(acc[o][1], vp[dx+2], wp);
                        ffma2(acc[o][2], vp[dx+4], wp);
                        ffma2(acc[o][3], vp[dx+6], wp);
                    }
                }
            }
        }
    };

    pref(0, 0); cpcommit();
#pragma unroll 1
    for (int ch = 0; ch < NCH; ch++){
        int cur = ch & 1;
        if (ch + 1 < NCH){ pref(cur ^ 1, (ch+1)*CH); cpcommit(); cpwait<1>(); }
        else cpwait<0>();
        __syncthreads();
        comp(cur);
        __syncthreads();
    }

    const int ocb = ocg*8 + tz*4;
    float* outb = out + (((size_t)(b*64 + ocb))*384 + (gy0 + ty))*384 + gx0 + tx*8;
#pragma unroll
    for (int o = 0; o < 4; o++){
        float bv = bias[ocb + o];
        float* op = outb + (size_t)o*NE;
#pragma unroll
        for (int j = 0; j < 4; j++){
            float2 v = up2(acc[o][j]);
            v.x += bv; v.y += bv;
            if (RELU){ v.x = fmaxf(v.x, 0.f); v.y = fmaxf(v.y, 0.f); }
            *reinterpret_cast<float2*>(op + j*2) = v;
        }
    }
}

// conv 64->2, simple scalar: block 256 = 16x16 px, 1 px x 2 oc per thread
__global__ void __launch_bounds__(256) conv_out_k(const float* __restrict__ in,
                                                  const float* __restrict__ w,
                                                  const float* __restrict__ bias)
{
    __shared__ float s_in[18*19];
    __shared__ float s_w[18];
    const int tid = threadIdx.x;
    const int tx = tid & 15, ty = tid >> 4;
    const int gx0 = blockIdx.x*16, gy0 = blockIdx.y*16;
    const int b = blockIdx.z;
    float a0 = 0.f, a1 = 0.f;
    const float* inb = in + (size_t)b*64*NE;
    for (int ci = 0; ci < 64; ci++){
        const float* pl = inb + (size_t)ci*NE;
        for (int i = tid; i < 18*18; i += 256){
            int rr = i / 18, cc = i - rr*18;
            int yy = gy0 - 1 + rr, xx = gx0 - 1 + cc;
            float v = 0.f;
            if ((unsigned)yy < 384u && (unsigned)xx < 384u) v = pl[yy*384 + xx];
            s_in[rr*19 + cc] = v;
        }
        if (tid < 18){
            int o = tid / 9, tp = tid % 9;
            s_w[tid] = w[((size_t)o*64 + ci)*9 + tp];
        }
        __syncthreads();
#pragma unroll
        for (int dy = 0; dy < 3; dy++)
#pragma unroll
            for (int dx = 0; dx < 3; dx++){
                float px = s_in[(ty+dy)*19 + tx + dx];
                a0 = fmaf(px, s_w[dy*3+dx], a0);
                a1 = fmaf(px, s_w[9+dy*3+dx], a1);
            }
        __syncthreads();
    }
    size_t o0 = (((size_t)(b*2 + 0))*384 + gy0 + ty)*384 + gx0 + tx;
    g_hplane[o0]      = a0 + bias[0];
    g_hplane[o0 + NE] = a1 + bias[1];
}

// rhs = under + lam*(x + h); r=p=rhs; xc=0; partial |rhs|^2
__global__ void __launch_bounds__(128) k_rhs(const float* __restrict__ under,
                                             const float* __restrict__ lam)
{
    __shared__ float sr[128];
    const int t = threadIdx.x, y = blockIdx.x, b = blockIdx.y;
    const float ls = lam[0];
    float acc = 0.f;
    for (int x = t; x < 384; x += 128){
        size_t i0 = (((size_t)(b*2))*384 + y)*384 + x;
        size_t i1 = i0 + NE;
        float rx = under[i0] + ls*(g_xplane[i0] + g_hplane[i0]);
        float ry = under[i1] + ls*(g_xplane[i1] + g_hplane[i1]);
        size_t ci = (size_t)b*NE + (size_t)y*384 + x;
        float2 rv = make_float2(rx, ry);
        g_r[ci] = rv; g_p[ci] = rv; g_xc[ci] = make_float2(0.f,0.f);
        acc += rx*rx + ry*ry;
    }
    sr[t] = acc; __syncthreads();
#pragma unroll
    for (int st = 64; st > 0; st >>= 1){ if (t < st) sr[t] += sr[t+st]; __syncthreads(); }
    if (t == 0) g_part1[b*384 + y] = sr[0];
}

// mode 0: rTr=sum(part1); 1: alpha=rTr/sum(part1); 2: beta=sum(part2)/rTr, rTr=sum
__global__ void k_scal(int mode)
{
    __shared__ float sr[256];
    const int t = threadIdx.x, b = blockIdx.x;
    const float* src = (mode == 2) ? (g_part2 + b*384) : (g_part1 + b*384);
    float v = src[t] + src[t + 128] + ((t < 128) ? src[t + 256] : 0.f);
    sr[t] = v; __syncthreads();
#pragma unroll
    for (int st = 128; st > 0; st >>= 1){ if (t < st) sr[t] += sr[t+st]; __syncthreads(); }
    if (t == 0){
        float s = sr[0];
        if (mode == 0) g_rTr[b] = s;
        else if (mode == 1) g_alpha[b] = g_rTr[b] / s;
        else { g_beta[b] = s / g_rTr[b]; g_rTr[b] = s; }
    }
}

// per (y,c,b): row of csm*p -> forward row FFT -> g_tmp
__global__ void __launch_bounds__(128) k_csmfft(const float* __restrict__ csm)
{
    __shared__ float2 line[384], scr[384];
    const int t = threadIdx.x, y = blockIdx.x, c = blockIdx.y, b = blockIdx.z;
    const float2* cl = ((const float2*)csm) + ((size_t)(b*CC + c)*384 + y)*384;
    const float2* pl = g_p + (size_t)b*NE + (size_t)y*384;
    for (int x = t; x < 384; x += 128) line[x] = f2mul(cl[x], pl[x]);
    __syncthreads();
    for (int i = t; i < 384; i += 128) scr[i] = line[perm384(i)];
    __syncthreads();
    fft384(scr, t, false);
    float2* o = g_tmp + ((size_t)(b*CC + c)*384 + y)*384;
    for (int x = t; x < 384; x += 128) o[x] = scr[x];
}

// per (x,c,b): column fwd FFT, mask, inverse FFT, in place
__global__ void __launch_bounds__(128) k_colmask(const float* __restrict__ mask)
{
    __shared__ float2 sA[384], sB[384];
    const int t = threadIdx.x, x = blockIdx.x, c = blockIdx.y, b = blockIdx.z;
    float2* col = g_tmp + ((size_t)(b*CC + c))*NE + x;
    for (int i = t; i < 384; i += 128) sA[i] = col[(size_t)perm384(i)*384];
    __syncthreads();
    fft384(sA, t, false);
    const float* mp = mask + (size_t)b*NE + x;
    for (int i = t; i < 384; i += 128){
        int pidx = perm384(i);
        float m = mp[(size_t)pidx*384];
        float2 v = sA[pidx];
        sB[i] = make_float2(v.x*m, v.y*m);
    }
    __syncthreads();
    fft384(sB, t, true);
    for (int i = t; i < 384; i += 128) col[(size_t)i*384] = sB[i];
}

// per (y,b): inverse row FFT per coil, acc conj(csm)*v, Ap = acc + lam*p, pAp partials
__global__ void __launch_bounds__(128) k_irow(const float* __restrict__ csm,
                                              const float* __restrict__ lam)
{
    __shared__ float2 scr[384];
    __shared__ float sr[128];
    const int t = threadIdx.x, y = blockIdx.x, b = blockIdx.y;
    float2 acc[3] = {{0.f,0.f},{0.f,0.f},{0.f,0.f}};
    for (int c = 0; c < CC; c++){
        const float2* row = g_tmp + ((size_t)(b*CC + c)*384 + y)*384;
        for (int i = t; i < 384; i += 128) scr[i] = row[perm384(i)];
        __syncthreads();
        fft384(scr, t, true);
        const float2* cl = ((const float2*)csm) + ((size_t)(b*CC + c)*384 + y)*384;
#pragma unroll
        for (int j = 0; j < 3; j++){
            int x = t + j*128;
            float2 cs = cl[x], v = scr[x];
            acc[j].x += cs.x*v.x + cs.y*v.y;
            acc[j].y += cs.x*v.y - cs.y*v.x;
        }
        __syncthreads();
    }
    const float ls = lam[0];
    float psum = 0.f;
#pragma unroll
    for (int j = 0; j < 3; j++){
        int x = t + j*128;
        size_t ci = (size_t)b*NE + (size_t)y*384 + x;
        float2 pv = g_p[ci];
        float2 ap = make_float2(acc[j].x + ls*pv.x, acc[j].y + ls*pv.y);
        g_Ap[ci] = ap;
        psum += pv.x*ap.x + pv.y*ap.y;
    }
    sr[t] = psum; __syncthreads();
#pragma unroll
    for (int st = 64; st > 0; st >>= 1){ if (t < st) sr[t] += sr[t+st]; __syncthreads(); }
    if (t == 0) g_part1[b*384 + y] = sr[0];
}

// x += alpha p; r -= alpha Ap; partial |r|^2
__global__ void __launch_bounds__(128) k_xr()
{
    __shared__ float sr[128];
    const int t = threadIdx.x, y = blockIdx.x, b = blockIdx.y;
    const float a = g_alpha[b];
    float acc = 0.f;
#pragma unroll
    for (int j = 0; j < 3; j++){
        int x = t + j*128;
        size_t ci = (size_t)b*NE + (size_t)y*384 + x;
        float2 pv = g_p[ci], ap = g_Ap[ci], xv = g_xc[ci], rv = g_r[ci];
        xv.x += a*pv.x; xv.y += a*pv.y;
        rv.x -= a*ap.x; rv.y -= a*ap.y;
        g_xc[ci] = xv; g_r[ci] = rv;
        acc += rv.x*rv.x + rv.y*rv.y;
    }
    sr[t] = acc; __syncthreads();
#pragma unroll
    for (int st = 64; st > 0; st >>= 1){ if (t < st) sr[t] += sr[t+st]; __syncthreads(); }
    if (t == 0) g_part2[b*384 + y] = sr[0];
}

__global__ void __launch_bounds__(128) k_p()
{
    const int t = threadIdx.x, y = blockIdx.x, b = blockIdx.y;
    const float be = g_beta[b];
#pragma unroll
    for (int j = 0; j < 3; j++){
        int x = t + j*128;
        size_t ci = (size_t)b*NE + (size_t)y*384 + x;
        float2 rv = g_r[ci], pv = g_p[ci];
        g_p[ci] = make_float2(rv.x + be*pv.x, rv.y + be*pv.y);
    }
}

__global__ void __launch_bounds__(128) k_back(float* __restrict__ out)
{
    const int t = threadIdx.x, y = blockIdx.x, b = blockIdx.y;
    for (int x = t; x < 384; x += 128){
        float2 v = g_xc[(size_t)b*NE + (size_t)y*384 + x];
        size_t i0 = (((size_t)(b*2))*384 + y)*384 + x;
        g_xplane[i0]      = v.x; out[i0]      = v.x;
        g_xplane[i0 + NE] = v.y; out[i0 + NE] = v.y;
    }
}

extern "C" void kernel_launch(void* const* d_in, const int* in_sizes, int n_in,
                              void* d_out, int out_size)
{
    const float* under = (const float*)d_in[0];
    const float* csm   = (const float*)d_in[1];
    const float* mask  = (const float*)d_in[2];
    const float* lam   = (const float*)d_in[3];
    const float* w_in  = (const float*)d_in[4];
    const float* b_in  = (const float*)d_in[5];
    const float* ws_mid= (const float*)d_in[6];
    const float* bs_mid= (const float*)d_in[7];
    const float* w_out = (const float*)d_in[8];
    const float* b_out = (const float*)d_in[9];
    float* out = (float*)d_out;

    k_twinit<<<1, 384>>>();
    k_copy<<<(BB*2*NE + 255)/256, 256>>>(under);
    k_wdup<<<(1152 + 7*36864 + 255)/256, 256>>>(w_in, ws_mid);

    dim3 cgrid(12, 12, BB*8);
    dim3 ogrid(24, 24, BB);
    dim3 rgrid(384, BB);
    dim3 fgrid(384, CC, BB);

    for (int layer = 0; layer < 5; layer++){
        conv_k<2, false><<<cgrid, 256>>>(g_xplane, g_actA, g_wdup, b_in);
        const float* src = g_actA; float* dst = g_actB;
        for (int v = 0; v < 7; v++){
            const float2* wv = g_wdup + 1152 + (size_t)v*36864;
            const float* bv = bs_mid + (size_t)v*64;
            if (v % 2 == 0) conv_k<64, true ><<<cgrid, 256>>>(src, dst, wv, bv);
            else            conv_k<64, false><<<cgrid, 256>>>(src, dst, wv, bv);
            const float* tmp = src; src = dst; dst = (float*)tmp;
        }
        conv_out_k<<<ogrid, 256>>>(src, w_out, b_out);
        k_rhs<<<rgrid, 128>>>(under, lam);
        k_scal<<<BB, 256>>>(0);
        for (int it = 0; it < 10; it++){
            k_csmfft<<<fgrid, 128>>>(csm);
            k_colmask<<<fgrid, 128>>>(mask);
            k_irow<<<rgrid, 128>>>(csm, lam);
            k_scal<<<BB, 256>>>(1);
            k_xr<<<rgrid, 128>>>();
            k_scal<<<BB, 256>>>(2);
            k_p<<<rgrid, 128>>>();
        }
        k_back<<<rgrid, 128>>>(out);
    }
}

// round 17
// speedup vs baseline: 1.4465x; 1.4465x over previous
#include <cuda_runtime.h>
#include <math.h>

#define HW 384
#define NE 147456
#define BB 4
#define CC 8
typedef unsigned long long ull;

__device__ float  g_actA[BB*64*NE];
__device__ float  g_actB[BB*64*NE];
__device__ float  g_xplane[BB*2*NE];
__device__ float  g_hplane[BB*2*NE];
__device__ float2 g_tmp[BB*CC*NE];
__device__ float2 g_r[BB*NE];
__device__ float2 g_p[BB*NE];
__device__ float2 g_xc[BB*NE];
__device__ float2 g_Ap[BB*NE];
__device__ float  g_part1[BB*384];
__device__ float  g_part2[BB*384];
__device__ float  g_rTr[BB];
__device__ float  g_alpha[BB];
__device__ float  g_beta[BB];
__device__ float2 g_tw[384];
// duplicated weights: conv_in [ci(2)][oc64][9] then 7 mid convs [ci64][oc64][9]
__device__ float2 g_wdup[1152 + 7*36864];

__device__ __forceinline__ ull pk2(float a, float b){
    ull r; asm("mov.b64 %0, {%1, %2};" : "=l"(r) : "f"(a), "f"(b)); return r;
}
__device__ __forceinline__ float2 up2(ull v){
    float2 r; asm("mov.b64 {%0, %1}, %2;" : "=f"(r.x), "=f"(r.y) : "l"(v)); return r;
}
__device__ __forceinline__ void ffma2(ull &d, ull a, ull b){
    asm("fma.rn.f32x2 %0, %1, %2, %0;" : "+l"(d) : "l"(a), "l"(b));
}
__device__ __forceinline__ void cpa4(unsigned s, const void* g){
    asm volatile("cp.async.ca.shared.global [%0], [%1], 4;" :: "r"(s), "l"(g));
}
__device__ __forceinline__ void cpa8(unsigned s, const void* g){
    asm volatile("cp.async.ca.shared.global [%0], [%1], 8;" :: "r"(s), "l"(g));
}
__device__ __forceinline__ void cpcommit(){ asm volatile("cp.async.commit_group;"); }
template<int N> __device__ __forceinline__ void cpwait(){
    asm volatile("cp.async.wait_group %0;" :: "n"(N));
}
__device__ __forceinline__ float2 f2add(float2 a, float2 b){ return make_float2(a.x+b.x, a.y+b.y); }
__device__ __forceinline__ float2 f2sub(float2 a, float2 b){ return make_float2(a.x-b.x, a.y-b.y); }
__device__ __forceinline__ float2 f2mul(float2 a, float2 b){
    return make_float2(a.x*b.x - a.y*b.y, a.x*b.y + a.y*b.x);
}
__device__ __forceinline__ int perm384(int i){
    return 3*(int)(__brev((unsigned)(i & 127)) >> 25) + (i >> 7);
}

// 384-pt FFT: input pre-permuted via perm384, blockDim.x == 128
__device__ void fft384(float2* Y, int t, bool inv)
{
#pragma unroll
    for (int s = 0; s < 7; s++){
        const int half = 1 << s;
#pragma unroll
        for (int kk = 0; kk < 2; kk++){
            int k = t + kk*128;
            if (k < 192){
                int sub = k >> 6, j = k & 63;
                int jl = j & (half - 1);
                int i0 = (sub << 7) + (((j >> s) << (s+1)) | jl);
                float2 w = g_tw[3*(jl << (6 - s))];
                if (inv) w.y = -w.y;
                float2 a = Y[i0], b = Y[i0 + half];
                float2 wb = f2mul(b, w);
                Y[i0]        = f2add(a, wb);
                Y[i0 + half] = f2sub(a, wb);
            }
        }
        __syncthreads();
    }
    {
        int m = t;
        float2 w1 = g_tw[m], w2 = g_tw[2*m];
        if (inv){ w1.y = -w1.y; w2.y = -w2.y; }
        float2 G0 = Y[m];
        float2 G1 = f2mul(Y[128 + m], w1);
        float2 G2 = f2mul(Y[256 + m], w2);
        const float wi = inv ? 0.86602540378443864676f : -0.86602540378443864676f;
        float2 A  = f2add(G1, G2);
        float2 Bd = f2sub(G1, G2);
        float2 X0 = f2add(G0, A);
        float2 T  = make_float2(G0.x - 0.5f*A.x, G0.y - 0.5f*A.y);
        float2 X1 = make_float2(T.x - wi*Bd.y, T.y + wi*Bd.x);
        float2 X2 = make_float2(T.x + wi*Bd.y, T.y - wi*Bd.x);
        if (inv){
            const float sc = 1.0f/384.0f;
            X0.x*=sc; X0.y*=sc; X1.x*=sc; X1.y*=sc; X2.x*=sc; X2.y*=sc;
        }
        __syncthreads();
        Y[m] = X0; Y[128 + m] = X1; Y[256 + m] = X2;
    }
    __syncthreads();
}

__global__ void k_twinit(){
    int t = threadIdx.x;
    if (t < 384){
        double th = -2.0 * 3.141592653589793238462643383279502884 * (double)t / 384.0;
        g_tw[t] = make_float2((float)cos(th), (float)sin(th));
    }
}
__global__ void k_copy(const float* __restrict__ src){
    int i = blockIdx.x*256 + threadIdx.x;
    if (i < BB*2*NE) g_xplane[i] = src[i];
}
// build duplicated-weight table
__global__ void k_wdup(const float* __restrict__ w_in, const float* __restrict__ ws_mid){
    int idx = blockIdx.x*256 + threadIdx.x;
    if (idx < 1152){
        int tap = idx % 9; int r = idx / 9;
        int oc = r % 64, ci = r / 64;
        float v = w_in[(size_t)(oc*2 + ci)*9 + tap];
        g_wdup[idx] = make_float2(v, v);
    }
    int m = idx - 1152;
    if (m >= 0 && m < 7*36864){
        int tap = m % 9; int r = m / 9;
        int oc = r % 64; r /= 64;
        int ci = r % 64; int v5 = r / 64;
        float v = ws_mid[((size_t)(v5*64 + oc)*64 + ci)*9 + tap];
        g_wdup[1152 + m] = make_float2(v, v);
    }
}

// ---------------- conv 3x3 SAME, 64 out channels, double-buffered (R15) ----
// block 256 = tx(4) x ty(32) x tz(2); tile 32x32; thread: 8 px x 8 oc (f32x2)
template<bool RELU>
__global__ void __launch_bounds__(256, 2) conv_k(const float* __restrict__ in,
                                                 float* __restrict__ out,
                                                 const float2* __restrict__ wd,
                                                 const float* __restrict__ bias,
                                                 int cin)
{
    __shared__ float  s_in[2][34*36];
    __shared__ float2 s_w[2][144];
    const int tid = threadIdx.x;
    const int tx = tid & 3;
    const int ty = (tid >> 2) & 31;
    const int tz = tid >> 7;
    const int gx0 = blockIdx.x*32, gy0 = blockIdx.y*32;
    const int b = blockIdx.z >> 2, ocg = blockIdx.z & 3;

    unsigned sin_b[2], sw_b[2];
    sin_b[0] = (unsigned)__cvta_generic_to_shared(&s_in[0][0]);
    sin_b[1] = (unsigned)__cvta_generic_to_shared(&s_in[1][0]);
    sw_b[0]  = (unsigned)__cvta_generic_to_shared(&s_w[0][0]);
    sw_b[1]  = (unsigned)__cvta_generic_to_shared(&s_w[1][0]);

    int soff[5], goff[5];
#pragma unroll
    for (int k = 0; k < 5; k++){
        int i = tid + 256*k;
        soff[k] = -1; goff[k] = -1;
        if (i < 34*34){
            int rr = i / 34, cc = i - rr*34;
            soff[k] = rr*36 + cc;
            int yy = gy0 - 1 + rr, xx = gx0 - 1 + cc;
            if ((unsigned)yy < 384u && (unsigned)xx < 384u) goff[k] = yy*384 + xx;
        }
    }

    ull acc[8][4];
#pragma unroll
    for (int o = 0; o < 8; o++)
#pragma unroll
        for (int j = 0; j < 4; j++) acc[o][j] = 0ULL;

    const float*  inb = in + (size_t)b*cin*NE;
    const float2* wb0 = wd + (size_t)(ocg*16)*9;

    auto pref = [&](int bi, int ci){
        const float* pl = inb + (size_t)ci*NE;
#pragma unroll
        for (int k = 0; k < 5; k++){
            if (soff[k] >= 0){
                if (goff[k] >= 0) cpa4(sin_b[bi] + soff[k]*4, pl + goff[k]);
                else {
                    float z = 0.f;
                    asm volatile("st.shared.f32 [%0], %1;" :: "r"(sin_b[bi] + soff[k]*4), "f"(z));
                }
            }
        }
        if (tid < 144) cpa8(sw_b[bi] + tid*8, wb0 + (size_t)ci*576 + tid);
    };
    auto comp = [&](int bi){
        const float*  sbuf = &s_in[bi][0];
        const float2* wrow = &s_w[bi][tz*72];
#pragma unroll
        for (int dy = 0; dy < 3; dy++){
            const float* row = &sbuf[(ty+dy)*36 + tx*8];
            float4 a4 = *(const float4*)row;
            float4 b4 = *(const float4*)(row + 4);
            float2 c2 = *(const float2*)(row + 8);
            float v[10] = {a4.x, a4.y, a4.z, a4.w, b4.x, b4.y, b4.z, b4.w, c2.x, c2.y};
            ull vp[9];
#pragma unroll
            for (int k = 0; k < 9; k++) vp[k] = pk2(v[k], v[k+1]);
#pragma unroll
            for (int dx = 0; dx < 3; dx++){
#pragma unroll
                for (int o = 0; o < 8; o++){
                    ull wp = *reinterpret_cast<const ull*>(&wrow[o*9 + dy*3 + dx]);
                    ffma2(acc[o][0], vp[dx+0], wp);
                    ffma2(acc[o][1], vp[dx+2], wp);
                    ffma2(acc[o][2], vp[dx+4], wp);
                    ffma2(acc[o][3], vp[dx+6], wp);
                }
            }
        }
    };

    pref(0, 0); cpcommit();
#pragma unroll 1
    for (int ci = 0; ci < cin; ci++){
        int cur = ci & 1;
        if (ci + 1 < cin){ pref(cur ^ 1, ci + 1); cpcommit(); cpwait<1>(); }
        else cpwait<0>();
        __syncthreads();
        comp(cur);
        __syncthreads();
    }

    const int ocb = ocg*16 + tz*8;
    float* outb = out + (((size_t)(b*64 + ocb))*384 + (gy0 + ty))*384 + gx0 + tx*8;
#pragma unroll
    for (int o = 0; o < 8; o++){
        float bv = bias[ocb + o];
        float* op = outb + (size_t)o*NE;
#pragma unroll
        for (int j = 0; j < 4; j++){
            float2 v = up2(acc[o][j]);
            v.x += bv; v.y += bv;
            if (RELU){ v.x = fmaxf(v.x, 0.f); v.y = fmaxf(v.y, 0.f); }
            *reinterpret_cast<float2*>(op + j*2) = v;
        }
    }
}

// conv 64->2, simple scalar: block 256 = 16x16 px, 1 px x 2 oc per thread
__global__ void __launch_bounds__(256) conv_out_k(const float* __restrict__ in,
                                                  const float* __restrict__ w,
                                                  const float* __restrict__ bias)
{
    __shared__ float s_in[18*19];
    __shared__ float s_w[18];
    const int tid = threadIdx.x;
    const int tx = tid & 15, ty = tid >> 4;
    const int gx0 = blockIdx.x*16, gy0 = blockIdx.y*16;
    const int b = blockIdx.z;
    float a0 = 0.f, a1 = 0.f;
    const float* inb = in + (size_t)b*64*NE;
    for (int ci = 0; ci < 64; ci++){
        const float* pl = inb + (size_t)ci*NE;
        for (int i = tid; i < 18*18; i += 256){
            int rr = i / 18, cc = i - rr*18;
            int yy = gy0 - 1 + rr, xx = gx0 - 1 + cc;
            float v = 0.f;
            if ((unsigned)yy < 384u && (unsigned)xx < 384u) v = pl[yy*384 + xx];
            s_in[rr*19 + cc] = v;
        }
        if (tid < 18){
            int o = tid / 9, tp = tid % 9;
            s_w[tid] = w[((size_t)o*64 + ci)*9 + tp];
        }
        __syncthreads();
#pragma unroll
        for (int dy = 0; dy < 3; dy++)
#pragma unroll
            for (int dx = 0; dx < 3; dx++){
                float px = s_in[(ty+dy)*19 + tx + dx];
                a0 = fmaf(px, s_w[dy*3+dx], a0);
                a1 = fmaf(px, s_w[9+dy*3+dx], a1);
            }
        __syncthreads();
    }
    size_t o0 = (((size_t)(b*2 + 0))*384 + gy0 + ty)*384 + gx0 + tx;
    g_hplane[o0]      = a0 + bias[0];
    g_hplane[o0 + NE] = a1 + bias[1];
}

// rhs = under + lam*(x + h); r=p=rhs; xc=0; partial |rhs|^2
__global__ void __launch_bounds__(128) k_rhs(const float* __restrict__ under,
                                             const float* __restrict__ lam)
{
    __shared__ float sr[128];
    const int t = threadIdx.x, y = blockIdx.x, b = blockIdx.y;
    const float ls = lam[0];
    float acc = 0.f;
    for (int x = t; x < 384; x += 128){
        size_t i0 = (((size_t)(b*2))*384 + y)*384 + x;
        size_t i1 = i0 + NE;
        float rx = under[i0] + ls*(g_xplane[i0] + g_hplane[i0]);
        float ry = under[i1] + ls*(g_xplane[i1] + g_hplane[i1]);
        size_t ci = (size_t)b*NE + (size_t)y*384 + x;
        float2 rv = make_float2(rx, ry);
        g_r[ci] = rv; g_p[ci] = rv; g_xc[ci] = make_float2(0.f,0.f);
        acc += rx*rx + ry*ry;
    }
    sr[t] = acc; __syncthreads();
#pragma unroll
    for (int st = 64; st > 0; st >>= 1){ if (t < st) sr[t] += sr[t+st]; __syncthreads(); }
    if (t == 0) g_part1[b*384 + y] = sr[0];
}

// mode 0: rTr=sum(part1); 1: alpha=rTr/sum(part1); 2: beta=sum(part2)/rTr, rTr=sum
__global__ void k_scal(int mode)
{
    __shared__ float sr[256];
    const int t = threadIdx.x, b = blockIdx.x;
    const float* src = (mode == 2) ? (g_part2 + b*384) : (g_part1 + b*384);
    float v = src[t] + src[t + 128] + ((t < 128) ? src[t + 256] : 0.f);
    sr[t] = v; __syncthreads();
#pragma unroll
    for (int st = 128; st > 0; st >>= 1){ if (t < st) sr[t] += sr[t+st]; __syncthreads(); }
    if (t == 0){
        float s = sr[0];
        if (mode == 0) g_rTr[b] = s;
        else if (mode == 1) g_alpha[b] = g_rTr[b] / s;
        else { g_beta[b] = s / g_rTr[b]; g_rTr[b] = s; }
    }
}

// per (y,c,b): row of csm*p -> forward row FFT -> g_tmp
__global__ void __launch_bounds__(128) k_csmfft(const float* __restrict__ csm)
{
    __shared__ float2 line[384], scr[384];
    const int t = threadIdx.x, y = blockIdx.x, c = blockIdx.y, b = blockIdx.z;
    const float2* cl = ((const float2*)csm) + ((size_t)(b*CC + c)*384 + y)*384;
    const float2* pl = g_p + (size_t)b*NE + (size_t)y*384;
    for (int x = t; x < 384; x += 128) line[x] = f2mul(cl[x], pl[x]);
    __syncthreads();
    for (int i = t; i < 384; i += 128) scr[i] = line[perm384(i)];
    __syncthreads();
    fft384(scr, t, false);
    float2* o = g_tmp + ((size_t)(b*CC + c)*384 + y)*384;
    for (int x = t; x < 384; x += 128) o[x] = scr[x];
}

// per (xg,c,b): 8-column tile staged in smem; per column: fwd FFT, mask, inv FFT
// Coalesced global access (64B row segments); smem tile row stride 18 words.
__global__ void __launch_bounds__(128) k_colmask(const float* __restrict__ mask)
{
    __shared__ float  T[384*18];   // float2 at word offset y*18 + 2x
    __shared__ float  M[384*8];    // mask at y*8 + x
    __shared__ float2 sA[384], sB[384];
    const int t = threadIdx.x, xg = blockIdx.x, c = blockIdx.y, b = blockIdx.z;
    float2* gp = g_tmp + ((size_t)(b*CC + c))*NE + xg*8;
    for (int i = t; i < 3072; i += 128){
        int y = i >> 3, x = i & 7;
        *(float2*)&T[y*18 + 2*x] = gp[(size_t)y*384 + x];
    }
    const float* mp = mask + (size_t)b*NE + xg*8;
    for (int i = t; i < 3072; i += 128){
        int y = i >> 3, x = i & 7;
        M[y*8 + x] = mp[(size_t)y*384 + x];
    }
    __syncthreads();
#pragma unroll 1
    for (int x = 0; x < 8; x++){
        for (int i = t; i < 384; i += 128) sA[i] = *(float2*)&T[perm384(i)*18 + 2*x];
        __syncthreads();
        fft384(sA, t, false);
        for (int i = t; i < 384; i += 128){
            int pi = perm384(i);
            float2 v = sA[pi]; float m = M[pi*8 + x];
            sB[i] = make_float2(v.x*m, v.y*m);
        }
        __syncthreads();
        fft384(sB, t, true);
        for (int i = t; i < 384; i += 128) *(float2*)&T[i*18 + 2*x] = sB[i];
        __syncthreads();
    }
    for (int i = t; i < 3072; i += 128){
        int y = i >> 3, x = i & 7;
        gp[(size_t)y*384 + x] = *(float2*)&T[y*18 + 2*x];
    }
}

// per (y,b): inverse row FFT per coil, acc conj(csm)*v, Ap = acc + lam*p, pAp partials
__global__ void __launch_bounds__(128) k_irow(const float* __restrict__ csm,
                                              const float* __restrict__ lam)
{
    __shared__ float2 scr[384];
    __shared__ float sr[128];
    const int t = threadIdx.x, y = blockIdx.x, b = blockIdx.y;
    float2 acc[3] = {{0.f,0.f},{0.f,0.f},{0.f,0.f}};
    for (int c = 0; c < CC; c++){
        const float2* row = g_tmp + ((size_t)(b*CC + c)*384 + y)*384;
        for (int i = t; i < 384; i += 128) scr[i] = row[perm384(i)];
        __syncthreads();
        fft384(scr, t, true);
        const float2* cl = ((const float2*)csm) + ((size_t)(b*CC + c)*384 + y)*384;
#pragma unroll
        for (int j = 0; j < 3; j++){
            int x = t + j*128;
            float2 cs = cl[x], v = scr[x];
            acc[j].x += cs.x*v.x + cs.y*v.y;
            acc[j].y += cs.x*v.y - cs.y*v.x;
        }
        __syncthreads();
    }
    const float ls = lam[0];
    float psum = 0.f;
#pragma unroll
    for (int j = 0; j < 3; j++){
        int x = t + j*128;
        size_t ci = (size_t)b*NE + (size_t)y*384 + x;
        float2 pv = g_p[ci];
        float2 ap = make_float2(acc[j].x + ls*pv.x, acc[j].y + ls*pv.y);
        g_Ap[ci] = ap;
        psum += pv.x*ap.x + pv.y*ap.y;
    }
    sr[t] = psum; __syncthreads();
#pragma unroll
    for (int st = 64; st > 0; st >>= 1){ if (t < st) sr[t] += sr[t+st]; __syncthreads(); }
    if (t == 0) g_part1[b*384 + y] = sr[0];
}

// x += alpha p; r -= alpha Ap; partial |r|^2
__global__ void __launch_bounds__(128) k_xr()
{
    __shared__ float sr[128];
    const int t = threadIdx.x, y = blockIdx.x, b = blockIdx.y;
    const float a = g_alpha[b];
    float acc = 0.f;
#pragma unroll
    for (int j = 0; j < 3; j++){
        int x = t + j*128;
        size_t ci = (size_t)b*NE + (size_t)y*384 + x;
        float2 pv = g_p[ci], ap = g_Ap[ci], xv = g_xc[ci], rv = g_r[ci];
        xv.x += a*pv.x; xv.y += a*pv.y;
        rv.x -= a*ap.x; rv.y -= a*ap.y;
        g_xc[ci] = xv; g_r[ci] = rv;
        acc += rv.x*rv.x + rv.y*rv.y;
    }
    sr[t] = acc; __syncthreads();
#pragma unroll
    for (int st = 64; st > 0; st >>= 1){ if (t < st) sr[t] += sr[t+st]; __syncthreads(); }
    if (t == 0) g_part2[b*384 + y] = sr[0];
}

__global__ void __launch_bounds__(128) k_p()
{
    const int t = threadIdx.x, y = blockIdx.x, b = blockIdx.y;
    const float be = g_beta[b];
#pragma unroll
    for (int j = 0; j < 3; j++){
        int x = t + j*128;
        size_t ci = (size_t)b*NE + (size_t)y*384 + x;
        float2 rv = g_r[ci], pv = g_p[ci];
        g_p[ci] = make_float2(rv.x + be*pv.x, rv.y + be*pv.y);
    }
}

__global__ void __launch_bounds__(128) k_back(float* __restrict__ out)
{
    const int t = threadIdx.x, y = blockIdx.x, b = blockIdx.y;
    for (int x = t; x < 384; x += 128){
        float2 v = g_xc[(size_t)b*NE + (size_t)y*384 + x];
        size_t i0 = (((size_t)(b*2))*384 + y)*384 + x;
        g_xplane[i0]      = v.x; out[i0]      = v.x;
        g_xplane[i0 + NE] = v.y; out[i0 + NE] = v.y;
    }
}

extern "C" void kernel_launch(void* const* d_in, const int* in_sizes, int n_in,
                              void* d_out, int out_size)
{
    const float* under = (const float*)d_in[0];
    const float* csm   = (const float*)d_in[1];
    const float* mask  = (const float*)d_in[2];
    const float* lam   = (const float*)d_in[3];
    const float* w_in  = (const float*)d_in[4];
    const float* b_in  = (const float*)d_in[5];
    const float* ws_mid= (const float*)d_in[6];
    const float* bs_mid= (const float*)d_in[7];
    const float* w_out = (const float*)d_in[8];
    const float* b_out = (const float*)d_in[9];
    float* out = (float*)d_out;

    k_twinit<<<1, 384>>>();
    k_copy<<<(BB*2*NE + 255)/256, 256>>>(under);
    k_wdup<<<(1152 + 7*36864 + 255)/256, 256>>>(w_in, ws_mid);

    dim3 cgrid(12, 12, BB*4);
    dim3 ogrid(24, 24, BB);
    dim3 rgrid(384, BB);
    dim3 fgrid(384, CC, BB);
    dim3 mgrid(48, CC, BB);

    for (int layer = 0; layer < 5; layer++){
        conv_k<false><<<cgrid, 256>>>(g_xplane, g_actA, g_wdup, b_in, 2);
        const float* src = g_actA; float* dst = g_actB;
        for (int v = 0; v < 7; v++){
            const float2* wv = g_wdup + 1152 + (size_t)v*36864;
            const float* bv = bs_mid + (size_t)v*64;
            if (v % 2 == 0) conv_k<true ><<<cgrid, 256>>>(src, dst, wv, bv, 64);
            else            conv_k<false><<<cgrid, 256>>>(src, dst, wv, bv, 64);
            const float* tmp = src; src = dst; dst = (float*)tmp;
        }
        conv_out_k<<<ogrid, 256>>>(src, w_out, b_out);
        k_rhs<<<rgrid, 128>>>(under, lam);
        k_scal<<<BB, 256>>>(0);
        for (int it = 0; it < 10; it++){
            k_csmfft<<<fgrid, 128>>>(csm);
            k_colmask<<<mgrid, 128>>>(mask);
            k_irow<<<rgrid, 128>>>(csm, lam);
            k_scal<<<BB, 256>>>(1);
            k_xr<<<rgrid, 128>>>();
            k_scal<<<BB, 256>>>(2);
            k_p<<<rgrid, 128>>>();
        }
        k_back<<<rgrid, 128>>>(out);
    }
}